// round 6
// baseline (speedup 1.0000x reference)
#include <cuda_runtime.h>
#include <math.h>

#define EMAX 4096
#define CAP (EMAX*(EMAX-1)/2)

// ---- device scratch (no allocations allowed) ----
__device__ float g_ang[EMAX];
__device__ float g_nx[EMAX], g_ny[EMAX], g_c[EMAX], g_mx[EMAX], g_my[EMAX];
__device__ float4 s_q[EMAX];                  // sorted-order (nx, ny, c, mx)
__device__ float  s_my[EMAX];                 // sorted-order my
__device__ int    s_oi[EMAX];                 // sorted-order original index
__device__ float  s_a[EMAX];                  // sorted angles (for emit: none needed; kept unused-safe)
__device__ int    g_fwd[EMAX], g_wrap[EMAX];
__device__ unsigned g_basei[EMAX];
__device__ unsigned g_count;
__device__ float g_buf[CAP];
__device__ unsigned g_hist16[65536];          // top-16-bit bins
__device__ unsigned g_hist16b[3*65536];       // low-16-bit bins per rank
__device__ unsigned g_pfx16[3];
__device__ unsigned g_rank[3];
__device__ float g_qval[3];
__device__ unsigned g_done;
__device__ double g_sum;

#define PI_F  3.14159274101257324f
#define THR_F 0.08726646259971647f

// ---------------------------------------------------------------------------
// K1: zero hist16 + accumulators, per-edge geometry.  <<<128,512>>>
// ---------------------------------------------------------------------------
__global__ void k_setup(const float* __restrict__ pos, const int* __restrict__ eidx, int E)
{
    int gtid = blockIdx.x * blockDim.x + threadIdx.x;
    if (gtid == 0) { g_sum = 0.0; g_done = 0u; }
    if (gtid < 65536) g_hist16[gtid] = 0u;

    if (gtid < E) {
        int e = gtid;
        int s = eidx[e];
        int d = eidx[E + e];
        float sx = pos[2*s], sy = pos[2*s+1];
        float dx = pos[2*d], dy = pos[2*d+1];
        float vx = dx - sx, vy = dy - sy;
        float len = fmaxf(sqrtf(vx*vx + vy*vy), 1e-8f);
        float ux = vx / len, uy = vy / len;
        float a = atan2f(uy, ux);
        a = fmodf(a, PI_F);
        if (a < 0.f) a += PI_F;
        g_ang[e] = a;
        float nx = -uy, ny = ux;
        g_nx[e] = nx;  g_ny[e] = ny;
        g_c[e]  = sx*nx + sy*ny;
        g_mx[e] = (sx + dx) * 0.5f;
        g_my[e] = (sy + dy) * 0.5f;
    }
}

// ---------------------------------------------------------------------------
// K2: bitonic sort + permute geometry + binary-search bounds + count scan.
// One block, 1024 threads. All searches hit SHARED memory.
// ---------------------------------------------------------------------------
__global__ void __launch_bounds__(1024, 1) k_sortb(int E)
{
    __shared__ float          sa[EMAX];
    __shared__ unsigned short si[EMAX];
    __shared__ unsigned       sscan[1024];

    int tid = threadIdx.x;

    for (int t = tid; t < EMAX; t += 1024) {
        sa[t] = (t < E) ? g_ang[t] : 3.4e38f;
        si[t] = (unsigned short)t;
    }
    __syncthreads();

    for (int k = 2; k <= EMAX; k <<= 1) {
        for (int j = k >> 1; j > 0; j >>= 1) {
            for (int t = tid; t < EMAX; t += 1024) {
                int p = t ^ j;
                if (p > t) {
                    bool up = ((t & k) == 0);
                    float va = sa[t], vb = sa[p];
                    if ((va > vb) == up) {
                        sa[t] = vb; sa[p] = va;
                        unsigned short ia = si[t]; si[t] = si[p]; si[p] = ia;
                    }
                }
            }
            __syncthreads();
        }
    }

    // permute geometry into sorted order (4096 random gathers, cheap)
    for (int t = tid; t < E; t += 1024) {
        int o = (int)si[t];
        s_q[t]  = make_float4(g_nx[o], g_ny[o], g_c[o], g_mx[o]);
        s_my[t] = g_my[o];
        s_oi[t] = o;
    }

    // binary-search bounds + counts (shared-memory searches), 4 edges/thread
    unsigned cnts[4];
    int      idxs[4];
    unsigned mysum = 0;
    #pragma unroll
    for (int q = 0; q < 4; q++) {
        int t = tid * 4 + q;
        idxs[q] = t;
        unsigned cnt = 0;
        if (t < E) {
            float ai = sa[t];
            // forward: first j in (t,E] with (aj - ai) <= THR false
            int lo = t + 1, hi = E;
            while (lo < hi) {
                int mid = (lo + hi) >> 1;
                if (sa[mid] - ai <= THR_F) lo = mid + 1; else hi = mid;
            }
            int fwd = lo;
            // wrap: first j in (t,E] with PI - (aj - ai) <= THR true
            lo = t + 1; hi = E;
            while (lo < hi) {
                int mid = (lo + hi) >> 1;
                if (PI_F - (sa[mid] - ai) <= THR_F) hi = mid; else lo = mid + 1;
            }
            int wrap = lo;
            if (wrap < fwd) wrap = fwd;
            g_fwd[t]  = fwd;
            g_wrap[t] = wrap;
            cnt = (unsigned)((fwd - (t + 1)) + (E - wrap));
        }
        cnts[q] = cnt;
        mysum += cnt;
    }
    __syncthreads();

    // 1024-wide inclusive scan of per-thread sums
    sscan[tid] = mysum;
    __syncthreads();
    #pragma unroll
    for (int off = 1; off < 1024; off <<= 1) {
        unsigned x = sscan[tid];
        unsigned a = (tid >= off) ? sscan[tid - off] : 0u;
        __syncthreads();
        sscan[tid] = x + a;
        __syncthreads();
    }
    unsigned exc = sscan[tid] - mysum;
    #pragma unroll
    for (int q = 0; q < 4; q++) {
        int t = idxs[q];
        if (t < E) g_basei[t] = exc;
        exc += cnts[q];
    }
    if (tid == 1023) g_count = sscan[1023];
}

// ---------------------------------------------------------------------------
// K3: dense emit (no contended atomics, coalesced) + hist16 REDs.
// Also zeroes hist16b for K5 (ordered by stream).  <<<128,512>>>
// ---------------------------------------------------------------------------
__global__ void k_emit(int E)
{
    int gtid = blockIdx.x * blockDim.x + threadIdx.x;
    #pragma unroll
    for (int k = 0; k < 3; k++) g_hist16b[k * 65536 + gtid] = 0u;

    const int nwarps = (gridDim.x * blockDim.x) >> 5;
    const int gwarp  = gtid >> 5;
    const int lane   = gtid & 31;

    for (int i = gwarp; i < E; i += nwarps) {
        int fwd   = g_fwd[i];
        int wrap  = g_wrap[i];
        int cnt_f = fwd - (i + 1);
        int cnt   = cnt_f + (E - wrap);
        if (cnt == 0) continue;
        unsigned ob = g_basei[i];
        float4 qi  = s_q[i];
        float  myi = s_my[i];
        int    oii = s_oi[i];
        for (int k = lane; k < cnt; k += 32) {
            int j = (k < cnt_f) ? (i + 1 + k) : (wrap + (k - cnt_f));
            float4 qj  = s_q[j];
            float  myj = s_my[j];
            int    oij = s_oi[j];
            float dist = (oii < oij)
                ? fabsf(fmaf(qi.x, qj.w, fmaf(qi.y, myj, -qi.z)))
                : fabsf(fmaf(qj.x, qi.w, fmaf(qj.y, myi, -qj.z)));
            g_buf[ob + k] = dist;
            atomicAdd(&g_hist16[__float_as_uint(dist) >> 16], 1u);
        }
    }
}

// ---------------------------------------------------------------------------
// K4: selection pass 1. One block, 1024 threads, 64 contiguous bins each.
// MLP-16 uint4 sums -> block scan -> owner reloads its bins (independent
// loads) and walks them in registers. NO dependent global-load chains.
// ---------------------------------------------------------------------------
__global__ void __launch_bounds__(1024, 1) k_sel1()
{
    __shared__ unsigned sscan[1024];
    int t = threadIdx.x;

    const uint4* h4 = (const uint4*)g_hist16;
    uint4 u[16];
    unsigned local = 0;
    #pragma unroll
    for (int k = 0; k < 16; k++) {
        u[k] = h4[t * 16 + k];
        local += u[k].x + u[k].y + u[k].z + u[k].w;
    }
    sscan[t] = local;
    __syncthreads();
    #pragma unroll
    for (int off = 1; off < 1024; off <<= 1) {
        unsigned x = sscan[t];
        unsigned a = (t >= off) ? sscan[t - off] : 0u;
        __syncthreads();
        sscan[t] = x + a;
        __syncthreads();
    }
    unsigned inc = sscan[t], exc = inc - local;

    unsigned n = g_count;
    int r0 = (int)(n/4) - 1; if (r0 < 0) r0 = 0;
    int r1 = (int)(n/2);
    int r2 = (int)((3*(long long)n)/4); if (r2 > (int)n - 1) r2 = (int)n - 1;
    if (r2 < 0) r2 = 0;
    unsigned rr[3] = {(unsigned)r0, (unsigned)r1, (unsigned)r2};

    #pragma unroll
    for (int s = 0; s < 3; s++) {
        unsigned r = rr[s];
        if (local && exc <= r && r < inc) {
            unsigned cum = exc;
            unsigned bins[64];
            #pragma unroll
            for (int k = 0; k < 16; k++) {
                bins[4*k+0] = u[k].x; bins[4*k+1] = u[k].y;
                bins[4*k+2] = u[k].z; bins[4*k+3] = u[k].w;
            }
            #pragma unroll
            for (int b = 0; b < 64; b++) {
                unsigned h = bins[b];
                if (cum + h > r) { g_pfx16[s] = (unsigned)(t*64 + b); g_rank[s] = r - cum; break; }
                cum += h;
            }
        }
    }
}

// ---------------------------------------------------------------------------
// K5: pass-2 histogram over g_buf.  <<<128,512>>>
// ---------------------------------------------------------------------------
__global__ void k_hist2()
{
    unsigned n  = g_count;
    unsigned p0 = g_pfx16[0], p1 = g_pfx16[1], p2 = g_pfx16[2];
    int stride = gridDim.x * blockDim.x;
    for (unsigned idx = blockIdx.x * blockDim.x + threadIdx.x; idx < n; idx += stride) {
        unsigned bits = __float_as_uint(g_buf[idx]);
        unsigned hi = bits >> 16, lo = bits & 0xFFFFu;
        if (hi == p0) atomicAdd(&g_hist16b[lo],          1u);
        if (hi == p1) atomicAdd(&g_hist16b[65536  + lo], 1u);
        if (hi == p2) atomicAdd(&g_hist16b[131072 + lo], 1u);
    }
}

// ---------------------------------------------------------------------------
// K6: selection pass 2. 3 blocks (one per rank), same structure as K4.
// ---------------------------------------------------------------------------
__global__ void __launch_bounds__(1024, 1) k_sel2()
{
    __shared__ unsigned sscan[1024];
    int s = blockIdx.x, t = threadIdx.x;
    const uint4* h4 = (const uint4*)(&g_hist16b[s * 65536]);

    uint4 u[16];
    unsigned local = 0;
    #pragma unroll
    for (int k = 0; k < 16; k++) {
        u[k] = h4[t * 16 + k];
        local += u[k].x + u[k].y + u[k].z + u[k].w;
    }
    sscan[t] = local;
    __syncthreads();
    #pragma unroll
    for (int off = 1; off < 1024; off <<= 1) {
        unsigned x = sscan[t];
        unsigned a = (t >= off) ? sscan[t - off] : 0u;
        __syncthreads();
        sscan[t] = x + a;
        __syncthreads();
    }
    unsigned inc = sscan[t], exc = inc - local;

    unsigned r = g_rank[s];
    if (local && exc <= r && r < inc) {
        unsigned cum = exc;
        unsigned bins[64];
        #pragma unroll
        for (int k = 0; k < 16; k++) {
            bins[4*k+0] = u[k].x; bins[4*k+1] = u[k].y;
            bins[4*k+2] = u[k].z; bins[4*k+3] = u[k].w;
        }
        #pragma unroll
        for (int b = 0; b < 64; b++) {
            unsigned h = bins[b];
            if (cum + h > r) {
                g_qval[s] = __uint_as_float((g_pfx16[s] << 16) | (unsigned)(t*64 + b));
                break;
            }
            cum += h;
        }
    }
}

// ---------------------------------------------------------------------------
// K7: hinge-loss sum (double) + fused finalize via done counter. <<<128,512>>>
// ---------------------------------------------------------------------------
__global__ void k_loss(float* __restrict__ out)
{
    unsigned n = g_count;
    float q1 = g_qval[0], mu = g_qval[1], q3 = g_qval[2];
    float margin = fmaxf(q3 - q1, 1e-6f) * 0.75f;   // iqr * 0.5 * 1.5

    double local = 0.0;
    int stride = gridDim.x * blockDim.x;
    for (unsigned idx = blockIdx.x * blockDim.x + threadIdx.x; idx < n; idx += stride) {
        float d = g_buf[idx];
        float v = fabsf(d - mu) - margin;
        if (v > 0.f) local += (double)v;
    }
    for (int o = 16; o; o >>= 1) local += __shfl_down_sync(0xFFFFFFFFu, local, o);
    __shared__ double shs[16];
    if ((threadIdx.x & 31) == 0) shs[threadIdx.x >> 5] = local;
    __syncthreads();
    if (threadIdx.x < 32) {
        double v = (threadIdx.x < (blockDim.x >> 5)) ? shs[threadIdx.x] : 0.0;
        for (int o = 16; o; o >>= 1) v += __shfl_down_sync(0xFFFFFFFFu, v, o);
        if (threadIdx.x == 0 && v != 0.0) atomicAdd(&g_sum, v);
    }

    __shared__ bool last;
    if (threadIdx.x == 0) {
        __threadfence();
        last = (atomicAdd(&g_done, 1u) == gridDim.x - 1);
    }
    __syncthreads();
    if (last && threadIdx.x == 0) {
        __threadfence();
        double denom = (double)(n > 0u ? n : 1u);
        out[0] = (float)(*(volatile double*)&g_sum / denom);
    }
}

// ---------------------------------------------------------------------------
extern "C" void kernel_launch(void* const* d_in, const int* in_sizes, int n_in,
                              void* d_out, int out_size)
{
    const float* pos  = (const float*)d_in[0];   // node_positions (B*N, 2)
    // d_in[1] = adjacency: unused
    const int*   eidx = (const int*)d_in[2];     // edge_index (2, E)
    float* out = (float*)d_out;

    int E = in_sizes[2] / 2;
    if (E > EMAX) E = EMAX;

    k_setup<<<128, 512>>>(pos, eidx, E);
    k_sortb<<<1, 1024>>>(E);
    k_emit<<<128, 512>>>(E);
    k_sel1<<<1, 1024>>>();
    k_hist2<<<128, 512>>>();
    k_sel2<<<3, 1024>>>();
    k_loss<<<128, 512>>>(out);
}